// round 1
// baseline (speedup 1.0000x reference)
#include <cuda_runtime.h>
#include <cuda_bf16.h>
#include <cstdint>

// Problem constants
#define B_    32
#define N_    64
#define H_    32
#define D_    20
#define E_    64
#define KTOT  1280            // D_*E_
#define NROWS (B_*N_*N_)      // 131072
#define NP1   65
#define TILE_M 128
#define KC    320             // K chunk held in SMEM
#define NCHUNKS 4
#define BSTR  328             // SMEM B row stride (bf16 elems): conflict-free LDS pattern

// Scratch (allocation-free contract: device globals)
__device__ __nv_bfloat16 g_M[H_ * KTOT];       // 80 KB, folded W3*W_edge, layout [g][k]
__device__ float         g_ei[(size_t)NROWS * H_];  // 16.8 MB GEMM output [row][g]

// ---------------------------------------------------------------------------
// Kernel 1: M[g][dd*64+e] = sum_h W3[dd][h][g] * W_edge[h][e]
// ---------------------------------------------------------------------------
__global__ void prep_M(const float* __restrict__ W_edge, const float* __restrict__ edw) {
    int idx = blockIdx.x * blockDim.x + threadIdx.x;
    if (idx >= H_ * KTOT) return;
    int g  = idx / KTOT;
    int k  = idx - g * KTOT;
    int dd = k >> 6;
    int e  = k & 63;
    float s = 0.f;
#pragma unroll
    for (int h = 0; h < 32; h++)
        s += edw[dd * 1024 + h * 32 + g] * W_edge[h * 64 + e];
    g_M[g * KTOT + k] = __float2bfloat16(s);
}

// ---------------------------------------------------------------------------
// Kernel 2: C[131072,32] = A[131072,1280](f32->bf16) x M^T, mma.m16n8k16
// ---------------------------------------------------------------------------
__device__ __forceinline__ uint32_t f2b(float2 v) {
    __nv_bfloat162 b = __float22bfloat162_rn(v);
    return *reinterpret_cast<uint32_t*>(&b);
}

__global__ void __launch_bounds__(256) gemm_k(const float* __restrict__ A) {
    __shared__ __nv_bfloat16 Bs[2][H_ * BSTR];   // 2 x 21 KB

    const int tid  = threadIdx.x;
    const int warp = tid >> 5;
    const int lane = tid & 31;
    const int q = lane >> 2;      // 0..7
    const int t = lane & 3;       // 0..3
    const int row0 = blockIdx.x * TILE_M + warp * 16;

    const float* ap0 = A + (size_t)(row0 + q) * KTOT + t * 2;
    const float* ap1 = ap0 + (size_t)8 * KTOT;

    float acc[4][4];
#pragma unroll
    for (int i = 0; i < 4; i++)
#pragma unroll
        for (int j = 0; j < 4; j++) acc[i][j] = 0.f;

    // ----- helpers -----
    // stage one K-chunk of M into SMEM (padded stride)
    auto loadB = [&](int chunk, int buf) {
#pragma unroll
        for (int i = 0; i < 5; i++) {
            int idx = tid + i * 256;          // 0..1279 (32 rows x 40 uint4)
            int g   = idx / 40;
            int kq  = idx - g * 40;
            uint4 v = *(const uint4*)(g_M + g * KTOT + chunk * KC + kq * 8);
            *(uint4*)(&Bs[buf][g * BSTR + kq * 8]) = v;
        }
    };
    // prefetch one k32 group of A fragments (8 float2 per lane)
    float2 f[2][8];
    auto loadA = [&](float2 (&dst)[8], int kc) {
#pragma unroll
        for (int u = 0; u < 2; u++) {
            int kb = kc + u * 16;
            dst[u * 4 + 0] = *(const float2*)(ap0 + kb);       // a0: row q,   k 0-7
            dst[u * 4 + 1] = *(const float2*)(ap1 + kb);       // a1: row q+8, k 0-7
            dst[u * 4 + 2] = *(const float2*)(ap0 + kb + 8);   // a2: row q,   k 8-15
            dst[u * 4 + 3] = *(const float2*)(ap1 + kb + 8);   // a3: row q+8, k 8-15
        }
    };

    loadB(0, 0);
    loadA(f[0], 0);
    __syncthreads();

    for (int c = 0; c < NCHUNKS; c++) {
        if (c + 1 < NCHUNKS) loadB(c + 1, (c + 1) & 1);
        const __nv_bfloat16* bs = Bs[c & 1];
#pragma unroll
        for (int s2 = 0; s2 < 10; s2++) {          // k32 double-steps
            const int kc    = c * KC + s2 * 32;
            const int knext = kc + 32;
            const int cur   = s2 & 1;
            if (knext < KTOT) loadA(f[cur ^ 1], knext);
            float2* fc = f[cur];
#pragma unroll
            for (int u = 0; u < 2; u++) {
                const int ks = (kc - c * KC) + u * 16;   // smem col base
                uint32_t a0 = f2b(fc[u * 4 + 0]);
                uint32_t a1 = f2b(fc[u * 4 + 1]);
                uint32_t a2 = f2b(fc[u * 4 + 2]);
                uint32_t a3 = f2b(fc[u * 4 + 3]);
#pragma unroll
                for (int nb = 0; nb < 4; nb++) {
                    const __nv_bfloat16* bp = bs + (nb * 8 + q) * BSTR + ks + t * 2;
                    uint32_t b0 = *(const uint32_t*)bp;
                    uint32_t b1 = *(const uint32_t*)(bp + 8);
                    asm volatile(
                        "mma.sync.aligned.m16n8k16.row.col.f32.bf16.bf16.f32 "
                        "{%0,%1,%2,%3}, {%4,%5,%6,%7}, {%8,%9}, {%0,%1,%2,%3};"
                        : "+f"(acc[nb][0]), "+f"(acc[nb][1]),
                          "+f"(acc[nb][2]), "+f"(acc[nb][3])
                        : "r"(a0), "r"(a1), "r"(a2), "r"(a3), "r"(b0), "r"(b1));
                }
            }
        }
        __syncthreads();
    }

    // C fragment: c0,c1 -> (row q, g 2t..2t+1); c2,c3 -> (row q+8)
#pragma unroll
    for (int nb = 0; nb < 4; nb++) {
        const int gc = nb * 8 + t * 2;
        *(float2*)&g_ei[(size_t)(row0 + q)     * H_ + gc] = make_float2(acc[nb][0], acc[nb][1]);
        *(float2*)&g_ei[(size_t)(row0 + q + 8) * H_ + gc] = make_float2(acc[nb][2], acc[nb][3]);
    }
}

// ---------------------------------------------------------------------------
// Kernel 3: assemble output (B,H,65,65)
// ---------------------------------------------------------------------------
__global__ void assemble(const float* __restrict__ attn_bias,
                         const int*   __restrict__ spatial_pos,
                         const float* __restrict__ spatial_emb,
                         const float* __restrict__ vd,
                         float*       __restrict__ out) {
    int o = blockIdx.x * blockDim.x + threadIdx.x;
    const int TOT = B_ * H_ * NP1 * NP1;
    if (o >= TOT) return;
    int j   = o % NP1;
    int tmp = o / NP1;
    int i   = tmp % NP1;
    tmp    /= NP1;
    int h   = tmp % H_;
    int b   = tmp / H_;

    float v = 2.f * attn_bias[(b * NP1 + i) * NP1 + j];
    if (i == 0) {
        v += vd[h];
    } else if (j == 0) {
        v += vd[h];
    } else {
        int p = (b * N_ + (i - 1)) * N_ + (j - 1);
        int s = spatial_pos[p];
        v += spatial_emb[s * H_ + h];
        int sp = (s <= 1) ? 1 : (s - 1);
        sp = min(sp, 20);
        v += g_ei[(size_t)p * H_ + h] / (float)sp;
    }
    out[o] = v;
}

// ---------------------------------------------------------------------------
extern "C" void kernel_launch(void* const* d_in, const int* in_sizes, int n_in,
                              void* d_out, int out_size) {
    // metadata order: node_features, attn_bias, spatial_pos, edge_input,
    //                 attn_edge_type, W_edge, spatial_emb, vd_weight, edge_dis_weight
    const float* attn_bias   = (const float*)d_in[1];
    const int*   spatial_pos = (const int*)  d_in[2];
    const float* edge_input  = (const float*)d_in[3];
    const float* W_edge      = (const float*)d_in[5];
    const float* spatial_emb = (const float*)d_in[6];
    const float* vd          = (const float*)d_in[7];
    const float* edw         = (const float*)d_in[8];
    float* out = (float*)d_out;

    prep_M<<<(H_ * KTOT + 255) / 256, 256>>>(W_edge, edw);
    gemm_k<<<NROWS / TILE_M, 256>>>(edge_input);
    const int tot = B_ * H_ * NP1 * NP1;
    assemble<<<(tot + 255) / 256, 256>>>(attn_bias, spatial_pos, spatial_emb, vd, out);
}